// round 8
// baseline (speedup 1.0000x reference)
#include <cuda_runtime.h>
#include <cuda_bf16.h>

// Problem constants: B=32, M=32768, D=128, R=64, W=129
#define RB_B 32
#define RB_M 32768
#define RB_D 128
#define RB_W 129
#define UNROLL 8

// out[b,m,:] = ring[b,m,:] unless off=(m-start[b]) mod M < W:
//   w = weights[b,off]; out = ring*(1-erase[b]*w) + write_gate[b]*w*write_vec[b,:]
//
// HBM-bound copy (512MB R + 512MB W compulsory). MLP_p1 = 8: eight
// independent front-batched LDG.128 per thread with streaming hints.

__global__ __launch_bounds__(256) void ring_update_kernel(
    const float4* __restrict__ ring4,     // B*M*D/4 float4
    const float4* __restrict__ wvec4,     // B*D/4 float4
    const float*  __restrict__ weights,   // B*W
    const float*  __restrict__ erase,     // B
    const float*  __restrict__ wgate,     // B
    const int*    __restrict__ idx,       // B*W
    float4*       __restrict__ out4)
{
    const int D4 = RB_D / 4;  // 32

    // Block covers UNROLL*256 = 2048 consecutive float4s (= 64 full rows).
    int g = blockIdx.x * (UNROLL * 256) + threadIdx.x;

    float4 cur[UNROLL];

    // Front-batched independent loads: MLP_p1 = 8
#pragma unroll
    for (int k = 0; k < UNROLL; k++) {
        cur[k] = __ldcs(&ring4[g + k * 256]);
    }

    // Whole block lies within one batch (2048 float4 << M*D4 = 1M per batch,
    // and batch boundaries are multiples of 2048): compute b once.
    int b = g >> 20;                    // (b*M + m)*32 + d4 ; M*D4 = 2^20
    int start = __ldg(&idx[b * RB_W]);
    float e  = __ldg(&erase[b]);
    float gt = __ldg(&wgate[b]);

#pragma unroll
    for (int k = 0; k < UNROLL; k++) {
        int v   = g + k * 256;
        int d4  = v & (D4 - 1);        // v % 32
        int row = v >> 5;              // b*M + m
        int m   = row & (RB_M - 1);
        int off = (m - start) & (RB_M - 1);

        if (off < RB_W) {
            float w = __ldg(&weights[b * RB_W + off]);
            float keep = 1.0f - e * w;
            float add  = gt * w;
            float4 wv = __ldg(&wvec4[b * D4 + d4]);
            cur[k].x = cur[k].x * keep + add * wv.x;
            cur[k].y = cur[k].y * keep + add * wv.y;
            cur[k].z = cur[k].z * keep + add * wv.z;
            cur[k].w = cur[k].w * keep + add * wv.w;
        }
    }

#pragma unroll
    for (int k = 0; k < UNROLL; k++) {
        __stcs(&out4[g + k * 256], cur[k]);
    }
}

extern "C" void kernel_launch(void* const* d_in, const int* in_sizes, int n_in,
                              void* d_out, int out_size)
{
    const float4* ring4   = (const float4*)d_in[0];
    const float4* wvec4   = (const float4*)d_in[1];
    const float*  weights = (const float*)d_in[2];
    const float*  erase   = (const float*)d_in[3];
    const float*  wgate   = (const float*)d_in[4];
    const int*    idx     = (const int*)d_in[5];
    float4*       out4    = (float4*)d_out;

    const long long total = (long long)RB_B * RB_M * (RB_D / 4);   // 2^25 float4
    const int threads = 256;
    const int per_block = threads * UNROLL;                        // 2048 float4
    const int blocks = (int)(total / per_block);                   // 16384 (exact)

    ring_update_kernel<<<blocks, threads>>>(ring4, wvec4, weights, erase, wgate, idx, out4);
}